// round 9
// baseline (speedup 1.0000x reference)
#include <cuda_runtime.h>
#include <cuda_bf16.h>

// x: [B=16, C=64, H=256, W=256] fp32; conv_w [1,2,7,7]; conv_b [1]
// out = x * sigmoid(conv7x7(concat(mean_c(x), max_c(x))) + b)
//
// Chunked L2 staging (4 batches = 64 MB per chunk) with read/write overlap:
//   red(0); for i: conv(i); fused{ mul(i) || red(i+1) }
// reduce leaves x[chunk] in L2; mul re-reads it as hits (ldcs) while the
// NEXT chunk's reduce streams from DRAM -> balanced R+W DRAM traffic.

#define B 16
#define C 64
#define HW 65536           // 256*256
#define HWf4 16384         // HW/4
#define PLANE (C * HW)     // 2^22 elements (16 MB)
#define NBCH 4             // batches per chunk

#define RED_BLKS 1024      // 64 f4-pixels per block, 4 thr/pixel x 16 ch
#define MUL_BLKS 4096      // 1024 f4 per block (4 per thread)

__device__ float g_att[B * 2 * HW];   // [b][{avg,max}][hw]
__device__ float g_s[B * HW];

__device__ __forceinline__ void f4add(float4& a, const float4 b) {
    a.x += b.x; a.y += b.y; a.z += b.z; a.w += b.w;
}
__device__ __forceinline__ void f4max(float4& a, const float4 b) {
    a.x = fmaxf(a.x, b.x); a.y = fmaxf(a.y, b.y);
    a.z = fmaxf(a.z, b.z); a.w = fmaxf(a.w, b.w);
}

// ---------------------------------------------------------------------------
// Reduce body: block bi in [0,1024) handles 64 f4-pixels of chunk br0.
// 4 threads per pixel (16 channels each), smem combine. Default-cached x
// loads so the chunk stays L2-resident for the following mul.
// ---------------------------------------------------------------------------
__device__ __forceinline__ void reduce_body(const float* __restrict__ x,
                                            int bi, int br0) {
    __shared__ float4 ssum[4][64];
    __shared__ float4 smax[4][64];

    const int px = threadIdx.x & 63;
    const int g  = threadIdx.x >> 6;            // 0..3
    const int id = bi * 64 + px;                // [0, 65536) f4 within chunk
    const int b  = br0 + (id >> 14);
    const int q4 = id & (HWf4 - 1);

    const float4* xb = reinterpret_cast<const float4*>(x + (size_t)b * PLANE);
    const int c0 = g * 16;

    float4 sum = xb[(size_t)c0 * HWf4 + q4];
    float4 mx  = sum;
#pragma unroll
    for (int c = 1; c < 16; c++) {
        float4 v = xb[(size_t)(c0 + c) * HWf4 + q4];
        f4add(sum, v);
        f4max(mx, v);
    }
    ssum[g][px] = sum;
    smax[g][px] = mx;
    __syncthreads();

    if (g == 0) {
        float4 s = ssum[0][px], m = smax[0][px];
#pragma unroll
        for (int gg = 1; gg < 4; gg++) {
            f4add(s, ssum[gg][px]);
            f4max(m, smax[gg][px]);
        }
        const float inv = 1.0f / 64.0f;
        float4* avg_out = reinterpret_cast<float4*>(g_att + (size_t)b * 2 * HW);
        float4* max_out = reinterpret_cast<float4*>(g_att + (size_t)b * 2 * HW + HW);
        avg_out[q4] = make_float4(s.x * inv, s.y * inv, s.z * inv, s.w * inv);
        max_out[q4] = m;
    }
}

__global__ void __launch_bounds__(256) k_reduce(const float* __restrict__ x, int br0) {
    reduce_body(x, blockIdx.x, br0);
}

// ---------------------------------------------------------------------------
// Fused: blocks [0,RED_BLKS) reduce chunk br0 (skipped if br0<0);
//        blocks [RED_BLKS, RED_BLKS+MUL_BLKS) do out = x*s for chunk bm0.
// ---------------------------------------------------------------------------
__global__ void __launch_bounds__(256)
k_fused(const float* __restrict__ x, float* __restrict__ out, int bm0, int br0) {
    if (blockIdx.x < RED_BLKS) {
        if (br0 < 0) return;
        reduce_body(x, blockIdx.x, br0);
    } else {
        const int blk = blockIdx.x - RED_BLKS;
        const size_t base = ((size_t)bm0 << 20) + (size_t)blk * 1024 + threadIdx.x;
        const int b = (int)(base >> 20);

        const float4* xf = reinterpret_cast<const float4*>(x);
        float4* of = reinterpret_cast<float4*>(out);
        const float4* sb = reinterpret_cast<const float4*>(g_s + (size_t)b * HW);

        float4 xv[4], sv[4];
#pragma unroll
        for (int k = 0; k < 4; k++) xv[k] = __ldcs(xf + base + k * 256);
#pragma unroll
        for (int k = 0; k < 4; k++) {
            int q4 = (int)((base + k * 256) & (HWf4 - 1));
            sv[k] = __ldg(sb + q4);
        }
#pragma unroll
        for (int k = 0; k < 4; k++) {
            xv[k].x *= sv[k].x; xv[k].y *= sv[k].y;
            xv[k].z *= sv[k].z; xv[k].w *= sv[k].w;
            __stcs(of + base + k * 256, xv[k]);
        }
    }
}

// ---------------------------------------------------------------------------
// Conv: 7x7 + bias + sigmoid -> g_s. 64x16 tile, register sliding window.
// ---------------------------------------------------------------------------
__global__ void __launch_bounds__(256)
k_conv(const float* __restrict__ cw, const float* __restrict__ cb, int b0) {
    __shared__ float s_avg[22 * 72];
    __shared__ float s_mx[22 * 72];
    __shared__ float s_w[98];
    __shared__ float s_b;

    const int b  = b0 + blockIdx.z;
    const int w0 = blockIdx.x * 64;
    const int h0 = blockIdx.y * 16;
    const int tid = threadIdx.x;

    if (tid < 98) s_w[tid] = cw[tid];
    if (tid == 98) s_b = cb[0];

    const float* avgp = g_att + (size_t)b * 2 * HW;
    const float* maxp = avgp + HW;

    for (int i = tid; i < 22 * 70; i += 256) {
        int dy = i / 70, dx = i - dy * 70;
        int hh = h0 - 3 + dy, ww = w0 - 3 + dx;
        float a = 0.f, m = 0.f;
        if (hh >= 0 && hh < 256 && ww >= 0 && ww < 256) {
            int ii = hh * 256 + ww;
            a = avgp[ii];
            m = maxp[ii];
        }
        s_avg[dy * 72 + dx] = a;
        s_mx[dy * 72 + dx]  = m;
    }
    __syncthreads();

    const int tx = tid & 15;
    const int ty = tid >> 4;
    const int ow0 = tx * 4;

    float a0 = s_b, a1 = a0, a2 = a0, a3 = a0;
#pragma unroll
    for (int kh = 0; kh < 7; kh++) {
        const float* ra = s_avg + (ty + kh) * 72 + ow0;
        const float* rm = s_mx  + (ty + kh) * 72 + ow0;
        float v[10];
#pragma unroll
        for (int j = 0; j < 10; j++) v[j] = ra[j];
#pragma unroll
        for (int kw = 0; kw < 7; kw++) {
            float wA = s_w[kh * 7 + kw];
            a0 = fmaf(wA, v[kw],     a0);
            a1 = fmaf(wA, v[kw + 1], a1);
            a2 = fmaf(wA, v[kw + 2], a2);
            a3 = fmaf(wA, v[kw + 3], a3);
        }
#pragma unroll
        for (int j = 0; j < 10; j++) v[j] = rm[j];
#pragma unroll
        for (int kw = 0; kw < 7; kw++) {
            float wM = s_w[49 + kh * 7 + kw];
            a0 = fmaf(wM, v[kw],     a0);
            a1 = fmaf(wM, v[kw + 1], a1);
            a2 = fmaf(wM, v[kw + 2], a2);
            a3 = fmaf(wM, v[kw + 3], a3);
        }
    }
    float4 sg;
    sg.x = 1.0f / (1.0f + __expf(-a0));
    sg.y = 1.0f / (1.0f + __expf(-a1));
    sg.z = 1.0f / (1.0f + __expf(-a2));
    sg.w = 1.0f / (1.0f + __expf(-a3));
    *reinterpret_cast<float4*>(g_s + (size_t)b * HW + (h0 + ty) * 256 + w0 + ow0) = sg;
}

// ---------------------------------------------------------------------------
extern "C" void kernel_launch(void* const* d_in, const int* in_sizes, int n_in,
                              void* d_out, int out_size) {
    const float* x  = (const float*)d_in[0];
    const float* cw = (const float*)d_in[1];
    const float* cb = (const float*)d_in[2];
    float* out = (float*)d_out;

    k_reduce<<<RED_BLKS, 256>>>(x, 0);

    for (int i = 0; i < B / NBCH; i++) {
        dim3 g2(4, 16, NBCH);
        k_conv<<<g2, 256>>>(cw, cb, i * NBCH);

        int br0 = (i + 1 < B / NBCH) ? (i + 1) * NBCH : -1;
        k_fused<<<RED_BLKS + MUL_BLKS, 256>>>(x, out, i * NBCH, br0);
    }
}

// round 10
// speedup vs baseline: 1.0756x; 1.0756x over previous
#include <cuda_runtime.h>
#include <cuda_bf16.h>

// x: [B=16, C=64, H=256, W=256] fp32; conv_w [1,2,7,7]; conv_b [1]
// out = x * sigmoid(conv7x7(concat(mean_c(x), max_c(x))) + b)
//
// 3-stage chunk pipeline, chunk = 2 batches (32 MB). Launch j runs
//   reduce(chunk j) || conv(chunk j-1) || mul(chunk j-2)
// (all deps cross launch boundaries). L2 live window = 3 chunks = 96 MB,
// so x is read from DRAM exactly once; mul reads it back as L2 hits while
// the next chunk's reduce streams in -> balanced R+W DRAM traffic and the
// conv bubble is hidden inside DRAM-bound launches.

#define B 16
#define C 64
#define HW 65536           // 256*256
#define HWf4 16384         // HW/4
#define PLANE (C * HW)     // 2^22 elements (16 MB)
#define NBCH 2             // batches per chunk (32 MB)
#define NCHUNK (B / NBCH)  // 8

#define RED_BLKS  512      // 64 f4-pixels/block, 4 thr/px x 16 ch
#define CONV_BLKS 128      // 2 batches x 64 tiles (64x16)
#define MUL_BLKS  2048     // 1024 f4/block (4 per thread)
#define TOT_BLKS  (RED_BLKS + CONV_BLKS + MUL_BLKS)   // 2688

__device__ float g_att[B * 2 * HW];   // [b][{avg,max}][hw]
__device__ float g_s[B * HW];

__device__ __forceinline__ void f4add(float4& a, const float4 b) {
    a.x += b.x; a.y += b.y; a.z += b.z; a.w += b.w;
}
__device__ __forceinline__ void f4max(float4& a, const float4 b) {
    a.x = fmaxf(a.x, b.x); a.y = fmaxf(a.y, b.y);
    a.z = fmaxf(a.z, b.z); a.w = fmaxf(a.w, b.w);
}

__global__ void __launch_bounds__(256)
k_step(const float* __restrict__ x,
       const float* __restrict__ cw,
       const float* __restrict__ cb,
       float* __restrict__ out,
       int br0, int bc0, int bm0) {     // first batch of each role's chunk, -1 = skip
    const int blk = blockIdx.x;
    const int tid = threadIdx.x;

    if (blk < RED_BLKS) {
        // ============ reduce(chunk br0): channel mean+max ============
        if (br0 < 0) return;
        __shared__ float4 ssum[4][64];
        __shared__ float4 smax[4][64];

        const int px = tid & 63;
        const int g  = tid >> 6;                 // 0..3
        const int id = blk * 64 + px;            // [0, NBCH*HWf4)
        const int b  = br0 + (id >> 14);
        const int q4 = id & (HWf4 - 1);

        const float4* xb = reinterpret_cast<const float4*>(x + (size_t)b * PLANE);
        const int c0 = g * 16;

        float4 sum = xb[(size_t)c0 * HWf4 + q4];     // default cache: stay in L2
        float4 mx  = sum;
#pragma unroll
        for (int c = 1; c < 16; c++) {
            float4 v = xb[(size_t)(c0 + c) * HWf4 + q4];
            f4add(sum, v);
            f4max(mx, v);
        }
        ssum[g][px] = sum;
        smax[g][px] = mx;
        __syncthreads();

        if (g == 0) {
            float4 s = ssum[0][px], m = smax[0][px];
#pragma unroll
            for (int gg = 1; gg < 4; gg++) {
                f4add(s, ssum[gg][px]);
                f4max(m, smax[gg][px]);
            }
            const float inv = 1.0f / 64.0f;
            float4* avg_out = reinterpret_cast<float4*>(g_att + (size_t)b * 2 * HW);
            float4* max_out = reinterpret_cast<float4*>(g_att + (size_t)b * 2 * HW + HW);
            avg_out[q4] = make_float4(s.x * inv, s.y * inv, s.z * inv, s.w * inv);
            max_out[q4] = m;
        }

    } else if (blk < RED_BLKS + CONV_BLKS) {
        // ============ conv(chunk bc0): 7x7 + bias + sigmoid ============
        if (bc0 < 0) return;
        __shared__ float s_avg[22 * 72];
        __shared__ float s_mx[22 * 72];
        __shared__ float s_w[98];
        __shared__ float s_b;

        const int idx = blk - RED_BLKS;          // [0, 128)
        const int b   = bc0 + (idx >> 6);
        const int t   = idx & 63;
        const int w0  = (t & 3) * 64;
        const int h0  = (t >> 2) * 16;

        if (tid < 98) s_w[tid] = cw[tid];
        if (tid == 98) s_b = cb[0];

        const float* avgp = g_att + (size_t)b * 2 * HW;
        const float* maxp = avgp + HW;

        for (int i = tid; i < 22 * 70; i += 256) {
            int dy = i / 70, dx = i - dy * 70;
            int hh = h0 - 3 + dy, ww = w0 - 3 + dx;
            float a = 0.f, m = 0.f;
            if (hh >= 0 && hh < 256 && ww >= 0 && ww < 256) {
                int ii = hh * 256 + ww;
                a = avgp[ii];
                m = maxp[ii];
            }
            s_avg[dy * 72 + dx] = a;
            s_mx[dy * 72 + dx]  = m;
        }
        __syncthreads();

        const int tx = tid & 15;
        const int ty = tid >> 4;
        const int ow0 = tx * 4;

        float a0 = s_b, a1 = a0, a2 = a0, a3 = a0;
#pragma unroll
        for (int kh = 0; kh < 7; kh++) {
            const float* ra = s_avg + (ty + kh) * 72 + ow0;
            const float* rm = s_mx  + (ty + kh) * 72 + ow0;
            float v[10];
#pragma unroll
            for (int j = 0; j < 10; j++) v[j] = ra[j];
#pragma unroll
            for (int kw = 0; kw < 7; kw++) {
                float wA = s_w[kh * 7 + kw];
                a0 = fmaf(wA, v[kw],     a0);
                a1 = fmaf(wA, v[kw + 1], a1);
                a2 = fmaf(wA, v[kw + 2], a2);
                a3 = fmaf(wA, v[kw + 3], a3);
            }
#pragma unroll
            for (int j = 0; j < 10; j++) v[j] = rm[j];
#pragma unroll
            for (int kw = 0; kw < 7; kw++) {
                float wM = s_w[49 + kh * 7 + kw];
                a0 = fmaf(wM, v[kw],     a0);
                a1 = fmaf(wM, v[kw + 1], a1);
                a2 = fmaf(wM, v[kw + 2], a2);
                a3 = fmaf(wM, v[kw + 3], a3);
            }
        }
        float4 sg;
        sg.x = 1.0f / (1.0f + __expf(-a0));
        sg.y = 1.0f / (1.0f + __expf(-a1));
        sg.z = 1.0f / (1.0f + __expf(-a2));
        sg.w = 1.0f / (1.0f + __expf(-a3));
        *reinterpret_cast<float4*>(g_s + (size_t)b * HW + (h0 + ty) * 256 + w0 + ow0) = sg;

    } else {
        // ============ mul(chunk bm0): out = x * s ============
        if (bm0 < 0) return;
        const int mblk = blk - (RED_BLKS + CONV_BLKS);   // [0, 2048)
        const size_t base = ((size_t)bm0 << 20) + (size_t)mblk * 1024 + tid;
        const int b = (int)(base >> 20);

        const float4* xf = reinterpret_cast<const float4*>(x);
        float4* of = reinterpret_cast<float4*>(out);
        const float4* sb = reinterpret_cast<const float4*>(g_s + (size_t)b * HW);

        float4 xv[4], sv[4];
#pragma unroll
        for (int k = 0; k < 4; k++) xv[k] = __ldcs(xf + base + k * 256);   // L2 hit, evict after
#pragma unroll
        for (int k = 0; k < 4; k++) {
            int q4 = (int)((base + k * 256) & (HWf4 - 1));
            sv[k] = __ldg(sb + q4);
        }
#pragma unroll
        for (int k = 0; k < 4; k++) {
            xv[k].x *= sv[k].x; xv[k].y *= sv[k].y;
            xv[k].z *= sv[k].z; xv[k].w *= sv[k].w;
            __stcs(of + base + k * 256, xv[k]);            // stream out, no L2 pollution
        }
    }
}

// ---------------------------------------------------------------------------
extern "C" void kernel_launch(void* const* d_in, const int* in_sizes, int n_in,
                              void* d_out, int out_size) {
    const float* x  = (const float*)d_in[0];
    const float* cw = (const float*)d_in[1];
    const float* cb = (const float*)d_in[2];
    float* out = (float*)d_out;

    for (int j = 0; j < NCHUNK + 2; j++) {
        int br0 = (j < NCHUNK)                ? j * NBCH       : -1;
        int bc0 = (j >= 1 && j - 1 < NCHUNK)  ? (j - 1) * NBCH : -1;
        int bm0 = (j >= 2 && j - 2 < NCHUNK)  ? (j - 2) * NBCH : -1;
        k_step<<<TOT_BLKS, 256>>>(x, cw, cb, out, br0, bc0, bm0);
    }
}